// round 1
// baseline (speedup 1.0000x reference)
#include <cuda_runtime.h>

// GAT_68367289417953: out = softmax(where(adj>0, (x @ x^T)/8, -1e12)) @ x
// x: [32, 2048, 64] fp32, adj: [2048, 2048] int32, out: [32, 2048, 64] fp32
//
// Flash-attention structure, zero global scratch. K tile == V tile (same x).
// CTA = (batch, 64-row q tile). 256 threads, 4x4 register microtiles.

constexpr int Bb = 32;
constexpr int Nn = 2048;
constexpr int Dd = 64;
constexpr int BM = 64;          // q rows per CTA
constexpr int BK = 64;          // k cols per tile
constexpr int PSTRIDE = BM + 1; // pad P rows to break bank conflicts

constexpr int SMEM_FLOATS = Dd * BM    /* Qst [d][q]  */
                          + Dd * BK    /* Kst [d][k]  */
                          + BK * Dd    /* Vs  [k][d]  */
                          + BK * PSTRIDE; /* Pst [k][q+1] */
constexpr int SMEM_BYTES = SMEM_FLOATS * 4 + BM * BK; // + mask bytes

__global__ __launch_bounds__(256, 2)
void gat_flash_kernel(const float* __restrict__ x,
                      const int*   __restrict__ adj,
                      float*       __restrict__ out)
{
    extern __shared__ float smem[];
    float* Qst = smem;                   // [d][q]   64x64 (transposed)
    float* Kst = Qst + Dd * BM;          // [d][k]   64x64 (transposed)
    float* Vs  = Kst + Dd * BK;          // [k][d]   64x64 (natural)
    float* Pst = Vs  + BK * Dd;          // [k][q]   64x65 (padded)
    unsigned char* Ms = (unsigned char*)(Pst + BK * PSTRIDE); // [q][k] bytes

    const int tid = threadIdx.x;
    const int tx  = tid & 15;
    const int ty  = tid >> 4;
    const int q0  = ty * 4;   // my 4 q rows (local)
    const int c0  = tx * 4;   // my 4 cols (k cols in S phase, d cols in O phase)

    const int qbase = blockIdx.x * BM;
    const int b     = blockIdx.y;
    const float* xb = x + (size_t)b * Nn * Dd;

    // ---- load Q tile, transposed to [d][q] ----
    #pragma unroll
    for (int r = 0; r < 4; r++) {
        int row = r * 16 + ty;
        float4 v = *reinterpret_cast<const float4*>(xb + (qbase + row) * Dd + c0);
        Qst[(c0 + 0) * BM + row] = v.x;
        Qst[(c0 + 1) * BM + row] = v.y;
        Qst[(c0 + 2) * BM + row] = v.z;
        Qst[(c0 + 3) * BM + row] = v.w;
    }

    float o[4][4];
    float m[4], l[4];
    #pragma unroll
    for (int i = 0; i < 4; i++) {
        m[i] = -1e30f;  // finite sentinel: exp(m_old - m_new) never NaNs
        l[i] = 0.0f;
        #pragma unroll
        for (int j = 0; j < 4; j++) o[i][j] = 0.0f;
    }

    for (int kt = 0; kt < Nn / BK; kt++) {
        const int kbase = kt * BK;
        __syncthreads();  // previous iter done reading Kst/Vs/Pst/Ms

        // ---- load K/V tile (same data: Kst transposed for QK^T, Vs natural for PV) ----
        #pragma unroll
        for (int r = 0; r < 4; r++) {
            int row = r * 16 + ty;
            float4 v = *reinterpret_cast<const float4*>(xb + (kbase + row) * Dd + c0);
            Kst[(c0 + 0) * BK + row] = v.x;
            Kst[(c0 + 1) * BK + row] = v.y;
            Kst[(c0 + 2) * BK + row] = v.z;
            Kst[(c0 + 3) * BK + row] = v.w;
            *reinterpret_cast<float4*>(Vs + row * Dd + c0) = v;
        }
        // ---- load adj tile -> byte mask ----
        #pragma unroll
        for (int r = 0; r < 4; r++) {
            int row = r * 16 + ty;
            int4 a = *reinterpret_cast<const int4*>(adj + (qbase + row) * Nn + kbase + c0);
            uchar4 mb;
            mb.x = (a.x > 0); mb.y = (a.y > 0); mb.z = (a.z > 0); mb.w = (a.w > 0);
            *reinterpret_cast<uchar4*>(Ms + row * BK + c0) = mb;
        }
        __syncthreads();

        // ---- S = Q K^T (4x4 microtile, contraction over d) ----
        float s[4][4];
        #pragma unroll
        for (int i = 0; i < 4; i++)
            #pragma unroll
            for (int j = 0; j < 4; j++) s[i][j] = 0.0f;

        const float* qp = Qst + q0;
        const float* kp = Kst + c0;
        #pragma unroll 8
        for (int dd = 0; dd < Dd; dd++) {
            float4 q4 = *reinterpret_cast<const float4*>(qp + dd * BM);
            float4 k4 = *reinterpret_cast<const float4*>(kp + dd * BK);
            float qv[4] = {q4.x, q4.y, q4.z, q4.w};
            float kv[4] = {k4.x, k4.y, k4.z, k4.w};
            #pragma unroll
            for (int i = 0; i < 4; i++)
                #pragma unroll
                for (int j = 0; j < 4; j++)
                    s[i][j] = fmaf(qv[i], kv[j], s[i][j]);
        }

        // ---- scale + mask (masked value is exactly -1e12, unscaled, like ref) ----
        #pragma unroll
        for (int i = 0; i < 4; i++) {
            uchar4 mb = *reinterpret_cast<const uchar4*>(Ms + (q0 + i) * BK + c0);
            s[i][0] = mb.x ? s[i][0] * 0.125f : -1e12f;
            s[i][1] = mb.y ? s[i][1] * 0.125f : -1e12f;
            s[i][2] = mb.z ? s[i][2] * 0.125f : -1e12f;
            s[i][3] = mb.w ? s[i][3] * 0.125f : -1e12f;
        }

        // ---- online softmax (row reductions across the 16 tx lanes) ----
        #pragma unroll
        for (int i = 0; i < 4; i++) {
            float mt = fmaxf(fmaxf(s[i][0], s[i][1]), fmaxf(s[i][2], s[i][3]));
            #pragma unroll
            for (int off = 1; off < 16; off <<= 1)
                mt = fmaxf(mt, __shfl_xor_sync(0xffffffffu, mt, off));
            float mn    = fmaxf(m[i], mt);
            float alpha = __expf(m[i] - mn);
            m[i] = mn;
            l[i] *= alpha;
            #pragma unroll
            for (int j = 0; j < 4; j++) o[i][j] *= alpha;

            float rs = 0.0f;
            #pragma unroll
            for (int j = 0; j < 4; j++) {
                float p = __expf(s[i][j] - mn);
                s[i][j] = p;
                rs += p;
            }
            #pragma unroll
            for (int off = 1; off < 16; off <<= 1)
                rs += __shfl_xor_sync(0xffffffffu, rs, off);
            l[i] += rs;
        }

        // ---- stage P transposed [k][q] (padded stride -> 2-way conflicts max) ----
        #pragma unroll
        for (int i = 0; i < 4; i++)
            #pragma unroll
            for (int j = 0; j < 4; j++)
                Pst[(c0 + j) * PSTRIDE + q0 + i] = s[i][j];
        __syncthreads();

        // ---- O += P V (contraction over k cols) ----
        #pragma unroll 8
        for (int kc = 0; kc < BK; kc++) {
            float4 v4 = *reinterpret_cast<const float4*>(Vs + kc * Dd + c0);
            float p0 = Pst[kc * PSTRIDE + q0 + 0];
            float p1 = Pst[kc * PSTRIDE + q0 + 1];
            float p2 = Pst[kc * PSTRIDE + q0 + 2];
            float p3 = Pst[kc * PSTRIDE + q0 + 3];
            float vv[4] = {v4.x, v4.y, v4.z, v4.w};
            float pp[4] = {p0, p1, p2, p3};
            #pragma unroll
            for (int i = 0; i < 4; i++)
                #pragma unroll
                for (int j = 0; j < 4; j++)
                    o[i][j] = fmaf(pp[i], vv[j], o[i][j]);
        }
    }

    // ---- epilogue: normalize by l, write out ----
    #pragma unroll
    for (int i = 0; i < 4; i++) {
        float inv = 1.0f / l[i];
        float4 r;
        r.x = o[i][0] * inv;
        r.y = o[i][1] * inv;
        r.z = o[i][2] * inv;
        r.w = o[i][3] * inv;
        *reinterpret_cast<float4*>(
            out + (size_t)b * Nn * Dd + (qbase + q0 + i) * Dd + c0) = r;
    }
}

extern "C" void kernel_launch(void* const* d_in, const int* in_sizes, int n_in,
                              void* d_out, int out_size)
{
    const float* x   = (const float*)d_in[0];
    const int*   adj = (const int*)d_in[1];
    float*       out = (float*)d_out;

    cudaFuncSetAttribute(gat_flash_kernel,
                         cudaFuncAttributeMaxDynamicSharedMemorySize, SMEM_BYTES);
    dim3 grid(Nn / BM, Bb);
    gat_flash_kernel<<<grid, 256, SMEM_BYTES>>>(x, adj, out);
}